// round 14
// baseline (speedup 1.0000x reference)
#include <cuda_runtime.h>
#include <cuda_fp16.h>
#include <cstdint>

#define H        64
#define NPIX     65536
#define LBATCH   8
#define NSPLIT   55                      // 8*55 = 440 CTAs ~ 148 SMs * 3 CTAs (1 wave)
#define NCTA     (LBATCH * NSPLIT)
#define NCHUNKS  1024                    // 64-pixel chunks per image

// scratch: per-CTA 3 GEMM tiles: [cta][gemm][64*64]
__device__ float g_part[(size_t)NCTA * 3 * H * H];
// per-reduce-block partial totals: [lc][16 blocks]
__device__ float g_bsum[LBATCH * 3 * 16];

#define BUF_BYTES 0x6000u                      // 3*4*4*32 uint4 = 24 KB per buffer
#define SMEM_BYTES (2 * BUF_BYTES)             // 48 KB

__device__ __forceinline__ uint32_t smem_u32(const void* p) {
    uint32_t a;
    asm("{ .reg .u64 t; cvta.to.shared.u64 t, %1; cvt.u32.u64 %0, t; }" : "=r"(a) : "l"(p));
    return a;
}
__device__ __forceinline__ unsigned pk(float lo, float hi) {  // f32x2 -> f16x2
    unsigned r; asm("cvt.rn.f16x2.f32 %0, %2, %1;" : "=r"(r) : "f"(lo), "f"(hi));
    return r;
}
__device__ __forceinline__ unsigned hm2(unsigned a, unsigned b) {
    unsigned r; asm("mul.rn.f16x2 %0, %1, %2;" : "=r"(r) : "r"(a), "r"(b));
    return r;
}
__device__ __forceinline__ float lg2a(float x) {
    float r; asm("lg2.approx.f32 %0, %1;" : "=f"(r) : "f"(x));
    return r;
}
__device__ __forceinline__ float sqrta(float x) {
    float r; asm("sqrt.approx.f32 %0, %1;" : "=f"(r) : "f"(x));
    return r;
}
__device__ __forceinline__ float rcpa(float x) {
    float r; asm("rcp.approx.ftz.f32 %0, %1;" : "=f"(r) : "f"(x));
    return r;
}
// two kernel values (pixels u0,u1 at same bin), sqrt-weight folded, via the
// product-reciprocal trick: ONE f32 MUFU per pair, f32 math until final pack.
__device__ __forceinline__ unsigned kv(float u0, float u1, unsigned sw2) {
    float a = fmaf(u0, u0, 1.0f);
    float b = fmaf(u1, u1, 1.0f);
    float r = rcpa(a * b);
    return hm2(pk(b * r, a * r), sw2);
}
__device__ __forceinline__ void mma16816(float* c, const unsigned* a, unsigned b0, unsigned b1) {
    asm volatile(
        "mma.sync.aligned.m16n8k16.row.col.f32.f16.f16.f32 "
        "{%0,%1,%2,%3}, {%4,%5,%6,%7}, {%8,%9}, {%0,%1,%2,%3};"
        : "+f"(c[0]), "+f"(c[1]), "+f"(c[2]), "+f"(c[3])
        : "r"(a[0]), "r"(a[1]), "r"(a[2]), "r"(a[3]), "r"(b0), "r"(b1));
}
__device__ __forceinline__ float shf(float v, int src) {
    return __shfl_sync(0xffffffffu, v, src);
}
__device__ __forceinline__ uint4 lds128(uint32_t a) {
    uint4 v;
    asm volatile("ld.shared.v4.b32 {%0,%1,%2,%3}, [%4];"
                 : "=r"(v.x), "=r"(v.y), "=r"(v.z), "=r"(v.w) : "r"(a));
    return v;
}
__device__ __forceinline__ void sts128(uint32_t a, uint4 v) {
    asm volatile("st.shared.v4.b32 [%0], {%1,%2,%3,%4};"
                 :: "r"(a), "r"(v.x), "r"(v.y), "r"(v.z), "r"(v.w) : "memory");
}

// 12 warps per CTA, 3 CTAs per SM (36 warps/SM). Warp w: g=w%3, h=w/3 (0..3).
// 64-px chunks, double-buffered, ONE barrier per chunk.
// Produce: warp (g,h) owns k-step h (pixels 16h..16h+16; lanes L and L+16
// duplicate pixel L&15 — coalesced), computes d_g + sw, shuffles to fragment
// order, emits 4 m-blocks of vec g's k-step h.
// Consume: GEMM g (A=img[g>>1], B=img[g?2:1]) quadrant (mi=h>>1, ni=h&1):
// 4 K-steps x (4 LDS.128 + 8 MMA). acc[2][4][4] = 32 regs.
// Buffer layout (bytes): ((vec*4 + kstep)*4 + m)*512 + L*16.
__global__ __launch_bounds__(384, 3) void hist_main(const float* __restrict__ x) {
    extern __shared__ uint4 img[];

    const int tid = threadIdx.x;
    const int L = tid & 31;
    const int w = tid >> 5;
    const int g = w % 3, h = w / 3;
    const int mi = h >> 1, ni = h & 1;
    const int bx = blockIdx.x;
    const int l = bx / NSPLIT, split = bx % NSPLIT;
    const int cbeg = (split * NCHUNKS) / NSPLIT;
    const int cend = ((split + 1) * NCHUNKS) / NSPLIT;
    // warp's pixel: chunk*64 + 16h + (L&15)
    const float* __restrict__ xp = x + (size_t)l * 3 * NPIX + 16 * h + (L & 15);

    const uint32_t sb = smem_u32(img);
    const int aimg = g >> 1;
    const int bimg = (g == 0) ? 1 : 2;
    uint32_t baseA = sb + (uint32_t)aimg * 8192 + (uint32_t)mi * 1024 + (uint32_t)L * 16;
    uint32_t baseB = sb + (uint32_t)bimg * 8192 + (uint32_t)ni * 1024 + (uint32_t)L * 16;
    uint32_t baseP = sb + (uint32_t)(g * 4 + h) * 2048 + (uint32_t)L * 16;

    float acc[2][4][4];
#pragma unroll
    for (int m = 0; m < 2; m++)
#pragma unroll
        for (int j = 0; j < 4; j++)
#pragma unroll
            for (int k = 0; k < 4; k++) acc[m][j][k] = 0.0f;

    const float DLT = (6.0f / 63.0f) * 50.0f;             // scaled bin spacing
    const int q = L & 3;
    const float SC = 34.65735903f;                        // ln(2)/sigma
    const float ro_base = -150.0f + (float)(L >> 2) * DLT;

    // prefetch first chunk
    float pi0 = xp[(size_t)cbeg * 64];
    float pi1 = xp[(size_t)cbeg * 64 + NPIX];
    float pi2 = xp[(size_t)cbeg * 64 + 2 * NPIX];

    float pd[4];        // fragment-ordered d values for k-step h
    unsigned ps[2];     // fragment-ordered packed sqrt-weights

    auto prep = [&](int ch) {
        float i0 = fminf(fmaxf(pi0, 0.0f), 1.0f);
        float i1 = fminf(fmaxf(pi1, 0.0f), 1.0f);
        float i2 = fminf(fmaxf(pi2, 0.0f), 1.0f);
        if (ch + 1 < cend) {
            pi0 = xp[(size_t)(ch + 1) * 64];
            pi1 = xp[(size_t)(ch + 1) * 64 + NPIX];
            pi2 = xp[(size_t)(ch + 1) * 64 + 2 * NPIX];
        }
        float l0 = lg2a(i0 + 1e-6f);
        float l1 = lg2a(i1 + 1e-6f);
        float l2 = lg2a(i2 + 1e-6f);
        float d = (g == 0) ? (l0 - l1) : (g == 1) ? (l0 - l2) : (l1 - l2);
        d *= SC;
        float s = fmaf(i0, i0, fmaf(i1, i1, fmaf(i2, i2, 1e-6f)));
        float sw = sqrta(sqrta(s));           // sqrt(Iy)
        pd[0] = shf(d, 2 * q);
        pd[1] = shf(d, 2 * q + 1);
        pd[2] = shf(d, 2 * q + 8);
        pd[3] = shf(d, 2 * q + 9);
        ps[0] = pk(shf(sw, 2 * q),     shf(sw, 2 * q + 1));
        ps[1] = pk(shf(sw, 2 * q + 8), shf(sw, 2 * q + 9));
    };
    auto produce = [&](uint32_t bp) {
#pragma unroll
        for (int m = 0; m < 4; m++) {         // mtile m: bins rl+16m, rl+16m+8
            const float o0 = fmaf((float)(16 * m), DLT, ro_base);
            const float o1 = o0 + 8.0f * DLT;
            uint4 v;
            v.x = kv(pd[0] - o0, pd[1] - o0, ps[0]);
            v.y = kv(pd[0] - o1, pd[1] - o1, ps[0]);
            v.z = kv(pd[2] - o0, pd[3] - o0, ps[1]);
            v.w = kv(pd[2] - o1, pd[3] - o1, ps[1]);
            sts128(bp + (uint32_t)(m * 512), v);
        }
    };
    auto consume = [&](uint32_t bA, uint32_t bB) {
#pragma unroll
        for (int k = 0; k < 4; k++) {
            uint4 A0 = lds128(bA + (uint32_t)(k * 2048));
            uint4 A1 = lds128(bA + (uint32_t)(k * 2048 + 512));
            uint4 W0 = lds128(bB + (uint32_t)(k * 2048));
            uint4 W1 = lds128(bB + (uint32_t)(k * 2048 + 512));
            mma16816(acc[0][0], (const unsigned*)&A0, W0.x, W0.z);
            mma16816(acc[1][0], (const unsigned*)&A1, W0.x, W0.z);
            mma16816(acc[0][1], (const unsigned*)&A0, W0.y, W0.w);
            mma16816(acc[1][1], (const unsigned*)&A1, W0.y, W0.w);
            mma16816(acc[0][2], (const unsigned*)&A0, W1.x, W1.z);
            mma16816(acc[1][2], (const unsigned*)&A1, W1.x, W1.z);
            mma16816(acc[0][3], (const unsigned*)&A0, W1.y, W1.w);
            mma16816(acc[1][3], (const unsigned*)&A1, W1.y, W1.w);
        }
    };

    const int nreg = cend - cbeg;
    // prologue: produce chunk cbeg into buf 0
    prep(cbeg);
    produce(baseP);
    __syncthreads();

#pragma unroll 1
    for (int r = 0; r < nreg - 1; r++) {
        const uint32_t cOff = (uint32_t)(r & 1) * BUF_BYTES;
        prep(cbeg + r + 1);
        produce(baseP + (cOff ^ BUF_BYTES));  // next chunk -> other buffer
        consume(baseA + cOff, baseB + cOff);  // this chunk
        __syncthreads();
    }
    consume(baseA + (uint32_t)((nreg - 1) & 1) * BUF_BYTES,
            baseB + (uint32_t)((nreg - 1) & 1) * BUF_BYTES);

    // store this warp's 32x32 quadrant (non-atomic, private slot)
    float* dst = g_part + ((size_t)bx * 3 + g) * (H * H);
    const int r = L >> 2;
    const int qq = (L & 3) * 2;
#pragma unroll
    for (int m = 0; m < 2; m++)
#pragma unroll
        for (int jl = 0; jl < 4; jl++) {
            const int row0 = (2 * mi + m) * 16 + r;
            const int col = (4 * ni + jl) * 8 + qq;
            *(float2*)(dst + row0 * H + col)       = make_float2(acc[m][jl][0], acc[m][jl][1]);
            *(float2*)(dst + (row0 + 8) * H + col) = make_float2(acc[m][jl][2], acc[m][jl][3]);
        }
}

// grid (16, 24), 256 threads. Sums NSPLIT splits with the channel reversal
// mapping, writes out and a per-block partial total (no atomics, no zeroing).
__global__ void hist_reduce(float* __restrict__ out) {
    const int lc = blockIdx.y;
    const int c = lc % 3, lidx = lc / 3;
    const int e = blockIdx.x * 256 + threadIdx.x;  // 0..4095
    const int u = e >> 6, v = e & 63;
    int se;
    if (c == 0)      se = e;                        // identity
    else if (c == 1) se = ((63 - u) << 6) | v;      // row reversal
    else             se = 4095 - e;                 // row+col reversal
    const float* __restrict__ src =
        g_part + ((size_t)(lidx * NSPLIT) * 3 + c) * (H * H) + se;
    float a0 = 0, a1 = 0, a2 = 0, a3 = 0, a4 = 0, a5 = 0, a6 = 0, a7 = 0;
    int sp = 0;
#pragma unroll 1
    for (; sp + 8 <= NSPLIT; sp += 8) {
        a0 += src[(size_t)(sp + 0) * 3 * (H * H)];
        a1 += src[(size_t)(sp + 1) * 3 * (H * H)];
        a2 += src[(size_t)(sp + 2) * 3 * (H * H)];
        a3 += src[(size_t)(sp + 3) * 3 * (H * H)];
        a4 += src[(size_t)(sp + 4) * 3 * (H * H)];
        a5 += src[(size_t)(sp + 5) * 3 * (H * H)];
        a6 += src[(size_t)(sp + 6) * 3 * (H * H)];
        a7 += src[(size_t)(sp + 7) * 3 * (H * H)];
    }
    for (; sp < NSPLIT; sp++) a0 += src[(size_t)sp * 3 * (H * H)];
    float s = ((a0 + a1) + (a2 + a3)) + ((a4 + a5) + (a6 + a7));
    out[lc * (H * H) + e] = s;

    __shared__ float red[256];
    red[threadIdx.x] = s;
    __syncthreads();
#pragma unroll
    for (int st = 128; st > 0; st >>= 1) {
        if (threadIdx.x < st) red[threadIdx.x] += red[threadIdx.x + st];
        __syncthreads();
    }
    if (threadIdx.x == 0)
        g_bsum[lc * 16 + blockIdx.x] = red[0];
}

// grid 384, 256 threads. Each block covers 256 contiguous outputs (same l).
__global__ void hist_norm(float* __restrict__ out) {
    __shared__ float red[48];
    const int l = blockIdx.x / 48;                  // 12288 per l / 256 = 48 blocks
    if (threadIdx.x < 48) red[threadIdx.x] = g_bsum[l * 48 + threadIdx.x];
    __syncthreads();
    float tot = 1e-6f;
#pragma unroll
    for (int k = 0; k < 48; k++) tot += red[k];
    const int idx = blockIdx.x * 256 + threadIdx.x;
    out[idx] = out[idx] / tot;
}

extern "C" void kernel_launch(void* const* d_in, const int* in_sizes, int n_in,
                              void* d_out, int out_size) {
    const float* x = (const float*)d_in[0];
    float* out = (float*)d_out;
    (void)in_sizes; (void)n_in; (void)out_size;

    cudaFuncSetAttribute(hist_main, cudaFuncAttributeMaxDynamicSharedMemorySize,
                         SMEM_BYTES);
    hist_main<<<NCTA, 384, SMEM_BYTES>>>(x);
    hist_reduce<<<dim3(16, 24), 256>>>(out);
    hist_norm<<<384, 256>>>(out);
}

// round 15
// speedup vs baseline: 1.2739x; 1.2739x over previous
#include <cuda_runtime.h>
#include <cuda_fp16.h>
#include <cstdint>

#define H        64
#define NPIX     65536
#define LBATCH   8
#define NSPLIT   37                      // 8*37 = 296 CTAs = 148 SMs * 2 CTAs (1 wave)
#define NCTA     (LBATCH * NSPLIT)
#define NCHUNKS  512                     // 128-pixel chunks per image

// scratch: per-CTA 3 GEMM tiles: [cta][gemm][64*64]
__device__ float g_part[(size_t)NCTA * 3 * H * H];
// per-CTA total mass (sum of all 3 tiles) for fused normalization
__device__ float g_psum[NCTA];

#define BUF_BYTES 0xC000u                      // 3*8*4*32 uint4 = 48 KB per buffer
#define SMEM_BYTES (2 * BUF_BYTES)             // 96 KB

__device__ __forceinline__ uint32_t smem_u32(const void* p) {
    uint32_t a;
    asm("{ .reg .u64 t; cvta.to.shared.u64 t, %1; cvt.u32.u64 %0, t; }" : "=r"(a) : "l"(p));
    return a;
}
__device__ __forceinline__ unsigned pk(float lo, float hi) {  // f32x2 -> f16x2
    unsigned r; asm("cvt.rn.f16x2.f32 %0, %2, %1;" : "=r"(r) : "f"(lo), "f"(hi));
    return r;
}
__device__ __forceinline__ unsigned hm2(unsigned a, unsigned b) {
    unsigned r; asm("mul.rn.f16x2 %0, %1, %2;" : "=r"(r) : "r"(a), "r"(b));
    return r;
}
__device__ __forceinline__ float lg2a(float x) {
    float r; asm("lg2.approx.f32 %0, %1;" : "=f"(r) : "f"(x));
    return r;
}
__device__ __forceinline__ float sqrta(float x) {
    float r; asm("sqrt.approx.f32 %0, %1;" : "=f"(r) : "f"(x));
    return r;
}
__device__ __forceinline__ float rcpa(float x) {
    float r; asm("rcp.approx.ftz.f32 %0, %1;" : "=f"(r) : "f"(x));
    return r;
}
// two kernel values (pixels u0,u1 at same bin), sqrt-weight folded, via the
// product-reciprocal trick: ONE f32 MUFU per pair, f32 math until final pack.
__device__ __forceinline__ unsigned kv(float u0, float u1, unsigned sw2) {
    float a = fmaf(u0, u0, 1.0f);
    float b = fmaf(u1, u1, 1.0f);
    float r = rcpa(a * b);
    return hm2(pk(b * r, a * r), sw2);
}
__device__ __forceinline__ void mma16816(float* c, const unsigned* a, unsigned b0, unsigned b1) {
    asm volatile(
        "mma.sync.aligned.m16n8k16.row.col.f32.f16.f16.f32 "
        "{%0,%1,%2,%3}, {%4,%5,%6,%7}, {%8,%9}, {%0,%1,%2,%3};"
        : "+f"(c[0]), "+f"(c[1]), "+f"(c[2]), "+f"(c[3])
        : "r"(a[0]), "r"(a[1]), "r"(a[2]), "r"(a[3]), "r"(b0), "r"(b1));
}
__device__ __forceinline__ float shf(float v, int src) {
    return __shfl_sync(0xffffffffu, v, src);
}
__device__ __forceinline__ uint4 lds128(uint32_t a) {
    uint4 v;
    asm volatile("ld.shared.v4.b32 {%0,%1,%2,%3}, [%4];"
                 : "=r"(v.x), "=r"(v.y), "=r"(v.z), "=r"(v.w) : "r"(a));
    return v;
}
__device__ __forceinline__ void sts128(uint32_t a, uint4 v) {
    asm volatile("st.shared.v4.b32 [%0], {%1,%2,%3,%4};"
                 :: "r"(a), "r"(v.x), "r"(v.y), "r"(v.z), "r"(v.w) : "memory");
}

// 12 warps per CTA. Warp w: g = w%3 (vector/GEMM id), h = w/3 in 0..3.
// 128-px chunks, software-pipelined: region r = [interleaved consume(chunk r,
// buf r&1) + prep/produce(chunk r+1, buf (r&1)^1)], one barrier per region.
// Buffer layout (bytes, per buffer): ((vec*8+st)*4+m)*512 + L*16.
__global__ __launch_bounds__(384, 2) void hist_main(const float* __restrict__ x) {
    extern __shared__ uint4 img[];

    const int tid = threadIdx.x;
    const int w = tid >> 5;
    const int L = tid & 31;
    const int g = w % 3, h = w / 3;
    const int mi = h >> 1, ni = h & 1;
    const int bx = blockIdx.x;
    const int l = bx / NSPLIT, split = bx % NSPLIT;
    const int cbeg = (split * NCHUNKS) / NSPLIT;
    const int cend = ((split + 1) * NCHUNKS) / NSPLIT;
    const float* __restrict__ xp = x + (size_t)l * 3 * NPIX + 32 * h + L;

    const uint32_t sb = smem_u32(img);
    const int aimg = g >> 1;                  // A-operand image per GEMM
    const int bimg = (g == 0) ? 1 : 2;        // B-operand image per GEMM
    uint32_t baseA = sb + (uint32_t)aimg * 16384 + (uint32_t)mi * 1024 + (uint32_t)L * 16;
    uint32_t baseB = sb + (uint32_t)bimg * 16384 + (uint32_t)ni * 1024 + (uint32_t)L * 16;
    uint32_t baseP = sb + (uint32_t)g * 16384 + (uint32_t)(2 * h) * 2048 + (uint32_t)L * 16;

    float acc[2][4][4];
#pragma unroll
    for (int m = 0; m < 2; m++)
#pragma unroll
        for (int j = 0; j < 4; j++)
#pragma unroll
            for (int k = 0; k < 4; k++) acc[m][j][k] = 0.0f;

    const float DLT = (6.0f / 63.0f) * 50.0f;             // scaled bin spacing
    const int q = L & 3;
    const float SC = 34.65735903f;            // ln(2)/sigma
    // hoisted bin-offset pairs per m-block: oo[2m]=o0(m), oo[2m+1]=o1(m)
    float oo[8];
#pragma unroll
    for (int m = 0; m < 8; m++)
        oo[m] = -150.0f + (float)((L >> 2) + 8 * m) * DLT;

    // prefetch first chunk (all 3 channels of this warp's 32 pixels)
    float pi0 = xp[(size_t)cbeg * 128];
    float pi1 = xp[(size_t)cbeg * 128 + NPIX];
    float pi2 = xp[(size_t)cbeg * 128 + 2 * NPIX];

    float pd[8];        // fragment-ordered d values, [si][4]
    unsigned ps[4];     // fragment-ordered packed sqrt-weights, [si][2]

    auto prep = [&](int ch) {
        float i0 = fminf(fmaxf(pi0, 0.0f), 1.0f);
        float i1 = fminf(fmaxf(pi1, 0.0f), 1.0f);
        float i2 = fminf(fmaxf(pi2, 0.0f), 1.0f);
        if (ch + 1 < cend) {
            pi0 = xp[(size_t)(ch + 1) * 128];
            pi1 = xp[(size_t)(ch + 1) * 128 + NPIX];
            pi2 = xp[(size_t)(ch + 1) * 128 + 2 * NPIX];
        }
        float l0 = lg2a(i0 + 1e-6f);
        float l1 = lg2a(i1 + 1e-6f);
        float l2 = lg2a(i2 + 1e-6f);
        float d = (g == 0) ? (l0 - l1) : (g == 1) ? (l0 - l2) : (l1 - l2);
        d *= SC;
        float s = fmaf(i0, i0, fmaf(i1, i1, fmaf(i2, i2, 1e-6f)));
        float sw = sqrta(sqrta(s));           // sqrt(Iy)
#pragma unroll
        for (int si = 0; si < 2; si++) {
            const int b0 = 16 * si + 2 * q;
            pd[4 * si + 0] = shf(d, b0);
            pd[4 * si + 1] = shf(d, b0 + 1);
            pd[4 * si + 2] = shf(d, b0 + 8);
            pd[4 * si + 3] = shf(d, b0 + 9);
            ps[2 * si + 0] = pk(shf(sw, b0),     shf(sw, b0 + 1));
            ps[2 * si + 1] = pk(shf(sw, b0 + 8), shf(sw, b0 + 9));
        }
    };

    const int nreg = cend - cbeg;
    // prologue: produce chunk cbeg into buf 0
    prep(cbeg);
#pragma unroll
    for (int k = 0; k < 8; k++) {
        const int si = k >> 2, m = k & 3;
        const float o0 = oo[2 * m], o1 = oo[2 * m + 1];
        uint4 v;
        v.x = kv(pd[4 * si + 0] - o0, pd[4 * si + 1] - o0, ps[2 * si]);
        v.y = kv(pd[4 * si + 0] - o1, pd[4 * si + 1] - o1, ps[2 * si]);
        v.z = kv(pd[4 * si + 2] - o0, pd[4 * si + 3] - o0, ps[2 * si + 1]);
        v.w = kv(pd[4 * si + 2] - o1, pd[4 * si + 3] - o1, ps[2 * si + 1]);
        sts128(baseP + (uint32_t)(si * 2048 + m * 512), v);
    }
    __syncthreads();

    int32_t pDelta = BUF_BYTES, cDelta = BUF_BYTES;
#pragma unroll 1
    for (int r = 0; r < nreg - 1; r++) {
        baseP += pDelta; pDelta = -pDelta;    // produce -> other buffer
        prep(cbeg + r + 1);
#pragma unroll
        for (int k = 0; k < 8; k++) {
            // consume K-step k from current buffer (immediate offsets)
            uint4 A0 = lds128(baseA + (uint32_t)(k * 2048));
            uint4 A1 = lds128(baseA + (uint32_t)(k * 2048 + 512));
            uint4 W0 = lds128(baseB + (uint32_t)(k * 2048));
            uint4 W1 = lds128(baseB + (uint32_t)(k * 2048 + 512));
            mma16816(acc[0][0], (const unsigned*)&A0, W0.x, W0.z);
            mma16816(acc[1][0], (const unsigned*)&A1, W0.x, W0.z);
            mma16816(acc[0][1], (const unsigned*)&A0, W0.y, W0.w);
            mma16816(acc[1][1], (const unsigned*)&A1, W0.y, W0.w);
            mma16816(acc[0][2], (const unsigned*)&A0, W1.x, W1.z);
            mma16816(acc[1][2], (const unsigned*)&A1, W1.x, W1.z);
            mma16816(acc[0][3], (const unsigned*)&A0, W1.y, W1.w);
            mma16816(acc[1][3], (const unsigned*)&A1, W1.y, W1.w);
            // produce block k of next chunk into the other buffer
            const int si = k >> 2, m = k & 3;
            const float o0 = oo[2 * m], o1 = oo[2 * m + 1];
            uint4 v;
            v.x = kv(pd[4 * si + 0] - o0, pd[4 * si + 1] - o0, ps[2 * si]);
            v.y = kv(pd[4 * si + 0] - o1, pd[4 * si + 1] - o1, ps[2 * si]);
            v.z = kv(pd[4 * si + 2] - o0, pd[4 * si + 3] - o0, ps[2 * si + 1]);
            v.w = kv(pd[4 * si + 2] - o1, pd[4 * si + 3] - o1, ps[2 * si + 1]);
            sts128(baseP + (uint32_t)(si * 2048 + m * 512), v);
        }
        __syncthreads();
        baseA += cDelta; baseB += cDelta; cDelta = -cDelta;
    }
    // final region: consume only
#pragma unroll
    for (int k = 0; k < 8; k++) {
        uint4 A0 = lds128(baseA + (uint32_t)(k * 2048));
        uint4 A1 = lds128(baseA + (uint32_t)(k * 2048 + 512));
        uint4 W0 = lds128(baseB + (uint32_t)(k * 2048));
        uint4 W1 = lds128(baseB + (uint32_t)(k * 2048 + 512));
        mma16816(acc[0][0], (const unsigned*)&A0, W0.x, W0.z);
        mma16816(acc[1][0], (const unsigned*)&A1, W0.x, W0.z);
        mma16816(acc[0][1], (const unsigned*)&A0, W0.y, W0.w);
        mma16816(acc[1][1], (const unsigned*)&A1, W0.y, W0.w);
        mma16816(acc[0][2], (const unsigned*)&A0, W1.x, W1.z);
        mma16816(acc[1][2], (const unsigned*)&A1, W1.x, W1.z);
        mma16816(acc[0][3], (const unsigned*)&A0, W1.y, W1.w);
        mma16816(acc[1][3], (const unsigned*)&A1, W1.y, W1.w);
    }

    // store this warp's 32x32 quadrant (non-atomic, private slot)
    float* dst = g_part + ((size_t)bx * 3 + g) * (H * H);
    const int r = L >> 2;
    const int qq = (L & 3) * 2;
#pragma unroll
    for (int m = 0; m < 2; m++)
#pragma unroll
        for (int jl = 0; jl < 4; jl++) {
            const int row0 = (2 * mi + m) * 16 + r;
            const int col = (4 * ni + jl) * 8 + qq;
            *(float2*)(dst + row0 * H + col)       = make_float2(acc[m][jl][0], acc[m][jl][1]);
            *(float2*)(dst + (row0 + 8) * H + col) = make_float2(acc[m][jl][2], acc[m][jl][3]);
        }

    // fused totals: per-warp sum of accs -> smem -> g_psum[bx]
    float wsum = 0.0f;
#pragma unroll
    for (int m = 0; m < 2; m++)
#pragma unroll
        for (int jl = 0; jl < 4; jl++)
            wsum += (acc[m][jl][0] + acc[m][jl][1]) + (acc[m][jl][2] + acc[m][jl][3]);
#pragma unroll
    for (int off = 16; off > 0; off >>= 1)
        wsum += __shfl_xor_sync(0xffffffffu, wsum, off);
    __syncthreads();                       // consumes of img are done; reuse as scratch
    float* sscr = (float*)img;
    if (L == 0) sscr[w] = wsum;
    __syncthreads();
    if (tid == 0) {
        float t = 0.0f;
#pragma unroll
        for (int k = 0; k < 12; k++) t += sscr[k];
        g_psum[bx] = t;
    }
}

// grid (16, 24), 256 threads. Sums NSPLIT splits with the channel reversal
// mapping AND normalizes by the per-sample total (from g_psum) in one pass.
__global__ void hist_reduce(float* __restrict__ out) {
    const int lc = blockIdx.y;
    const int c = lc % 3, lidx = lc / 3;
    const int e = blockIdx.x * 256 + threadIdx.x;  // 0..4095
    const int u = e >> 6, v = e & 63;
    int se;
    if (c == 0)      se = e;                        // identity
    else if (c == 1) se = ((63 - u) << 6) | v;      // row reversal
    else             se = 4095 - e;                 // row+col reversal

    // per-sample total from per-CTA partials (kernel boundary = all written)
    __shared__ float tshare[NSPLIT];
    if (threadIdx.x < NSPLIT)
        tshare[threadIdx.x] = g_psum[lidx * NSPLIT + threadIdx.x];
    __syncthreads();
    float tot = 1e-6f;
#pragma unroll
    for (int k = 0; k < NSPLIT; k++) tot += tshare[k];   // broadcast LDS
    const float inv = 1.0f / tot;

    const float* __restrict__ src =
        g_part + ((size_t)(lidx * NSPLIT) * 3 + c) * (H * H) + se;
    float a0 = 0, a1 = 0, a2 = 0, a3 = 0, a4 = 0, a5 = 0, a6 = 0, a7 = 0;
    int sp = 0;
#pragma unroll 1
    for (; sp + 8 <= NSPLIT; sp += 8) {
        a0 += src[(size_t)(sp + 0) * 3 * (H * H)];
        a1 += src[(size_t)(sp + 1) * 3 * (H * H)];
        a2 += src[(size_t)(sp + 2) * 3 * (H * H)];
        a3 += src[(size_t)(sp + 3) * 3 * (H * H)];
        a4 += src[(size_t)(sp + 4) * 3 * (H * H)];
        a5 += src[(size_t)(sp + 5) * 3 * (H * H)];
        a6 += src[(size_t)(sp + 6) * 3 * (H * H)];
        a7 += src[(size_t)(sp + 7) * 3 * (H * H)];
    }
    for (; sp < NSPLIT; sp++) a0 += src[(size_t)sp * 3 * (H * H)];
    float s = ((a0 + a1) + (a2 + a3)) + ((a4 + a5) + (a6 + a7));
    out[lc * (H * H) + e] = s * inv;
}

extern "C" void kernel_launch(void* const* d_in, const int* in_sizes, int n_in,
                              void* d_out, int out_size) {
    const float* x = (const float*)d_in[0];
    float* out = (float*)d_out;
    (void)in_sizes; (void)n_in; (void)out_size;

    cudaFuncSetAttribute(hist_main, cudaFuncAttributeMaxDynamicSharedMemorySize,
                         SMEM_BYTES);
    hist_main<<<NCTA, 384, SMEM_BYTES>>>(x);
    hist_reduce<<<dim3(16, 24), 256>>>(out);
}

// round 16
// speedup vs baseline: 1.3069x; 1.0259x over previous
#include <cuda_runtime.h>
#include <cuda_fp16.h>
#include <cstdint>

#define H        64
#define NPIX     65536
#define LBATCH   8
#define NSPLIT   37                      // 8*37 = 296 CTAs = 148 SMs * 2 CTAs (1 wave)
#define NCTA     (LBATCH * NSPLIT)
#define NCHUNKS  512                     // 128-pixel chunks per image

// scratch: per-CTA 3 GEMM tiles: [cta][gemm][64*64]
__device__ float g_part[(size_t)NCTA * 3 * H * H];
// per-CTA total mass (sum of all 3 tiles) for fused normalization
__device__ float g_psum[NCTA];

#define BUF_BYTES 0xC000u                      // 3*8*4*32 uint4 = 48 KB per buffer
#define SMEM_BYTES (2 * BUF_BYTES)             // 96 KB

__device__ __forceinline__ uint32_t smem_u32(const void* p) {
    uint32_t a;
    asm("{ .reg .u64 t; cvta.to.shared.u64 t, %1; cvt.u32.u64 %0, t; }" : "=r"(a) : "l"(p));
    return a;
}
__device__ __forceinline__ unsigned pk(float lo, float hi) {  // f32x2 -> f16x2
    unsigned r; asm("cvt.rn.f16x2.f32 %0, %2, %1;" : "=r"(r) : "f"(lo), "f"(hi));
    return r;
}
__device__ __forceinline__ unsigned hm2(unsigned a, unsigned b) {
    unsigned r; asm("mul.rn.f16x2 %0, %1, %2;" : "=r"(r) : "r"(a), "r"(b));
    return r;
}
__device__ __forceinline__ float lg2a(float x) {
    float r; asm("lg2.approx.f32 %0, %1;" : "=f"(r) : "f"(x));
    return r;
}
__device__ __forceinline__ float sqrta(float x) {
    float r; asm("sqrt.approx.f32 %0, %1;" : "=f"(r) : "f"(x));
    return r;
}
__device__ __forceinline__ float rcpa(float x) {
    float r; asm("rcp.approx.ftz.f32 %0, %1;" : "=f"(r) : "f"(x));
    return r;
}
// two kernel values (pixels u0,u1 at same bin), sqrt-weight folded, via the
// product-reciprocal trick: ONE f32 MUFU per pair, f32 math until final pack.
__device__ __forceinline__ unsigned kv(float u0, float u1, unsigned sw2) {
    float a = fmaf(u0, u0, 1.0f);
    float b = fmaf(u1, u1, 1.0f);
    float r = rcpa(a * b);
    return hm2(pk(b * r, a * r), sw2);
}
__device__ __forceinline__ void mma16816(float* c, const unsigned* a, unsigned b0, unsigned b1) {
    asm volatile(
        "mma.sync.aligned.m16n8k16.row.col.f32.f16.f16.f32 "
        "{%0,%1,%2,%3}, {%4,%5,%6,%7}, {%8,%9}, {%0,%1,%2,%3};"
        : "+f"(c[0]), "+f"(c[1]), "+f"(c[2]), "+f"(c[3])
        : "r"(a[0]), "r"(a[1]), "r"(a[2]), "r"(a[3]), "r"(b0), "r"(b1));
}
__device__ __forceinline__ float shf(float v, int src) {
    return __shfl_sync(0xffffffffu, v, src);
}
__device__ __forceinline__ uint4 lds128(uint32_t a) {
    uint4 v;
    asm volatile("ld.shared.v4.b32 {%0,%1,%2,%3}, [%4];"
                 : "=r"(v.x), "=r"(v.y), "=r"(v.z), "=r"(v.w) : "r"(a));
    return v;
}
__device__ __forceinline__ void sts128(uint32_t a, uint4 v) {
    asm volatile("st.shared.v4.b32 [%0], {%1,%2,%3,%4};"
                 :: "r"(a), "r"(v.x), "r"(v.y), "r"(v.z), "r"(v.w) : "memory");
}

// 12 warps per CTA. Warp w: g = w%3 (vector/GEMM id), h = w/3 in 0..3.
// 128-px chunks, software-pipelined: region r = [interleaved consume(chunk r,
// buf r&1) + prep/produce(chunk r+1, buf (r&1)^1)], one barrier per region.
// Buffer layout (bytes, per buffer): ((vec*8+st)*4+m)*512 + L*16.
__global__ __launch_bounds__(384, 2) void hist_main(const float* __restrict__ x) {
    extern __shared__ uint4 img[];

    const int tid = threadIdx.x;
    const int w = tid >> 5;
    const int L = tid & 31;
    const int g = w % 3, h = w / 3;
    const int mi = h >> 1, ni = h & 1;
    const int bx = blockIdx.x;
    const int l = bx / NSPLIT, split = bx % NSPLIT;
    const int cbeg = (split * NCHUNKS) / NSPLIT;
    const int cend = ((split + 1) * NCHUNKS) / NSPLIT;
    const float* __restrict__ xp = x + (size_t)l * 3 * NPIX + 32 * h + L;

    const uint32_t sb = smem_u32(img);
    const int aimg = g >> 1;                  // A-operand image per GEMM
    const int bimg = (g == 0) ? 1 : 2;        // B-operand image per GEMM
    uint32_t baseA = sb + (uint32_t)aimg * 16384 + (uint32_t)mi * 1024 + (uint32_t)L * 16;
    uint32_t baseB = sb + (uint32_t)bimg * 16384 + (uint32_t)ni * 1024 + (uint32_t)L * 16;
    uint32_t baseP = sb + (uint32_t)g * 16384 + (uint32_t)(2 * h) * 2048 + (uint32_t)L * 16;

    float acc[2][4][4];
#pragma unroll
    for (int m = 0; m < 2; m++)
#pragma unroll
        for (int j = 0; j < 4; j++)
#pragma unroll
            for (int k = 0; k < 4; k++) acc[m][j][k] = 0.0f;

    const float DLT = (6.0f / 63.0f) * 50.0f;             // scaled bin spacing
    const int q = L & 3;
    const float SC = 34.65735903f;            // ln(2)/sigma
    // hoisted bin-offset pairs per m-block: oo[2m]=o0(m), oo[2m+1]=o1(m)
    float oo[8];
#pragma unroll
    for (int m = 0; m < 8; m++)
        oo[m] = -150.0f + (float)((L >> 2) + 8 * m) * DLT;

    // prefetch first chunk (all 3 channels of this warp's 32 pixels)
    float pi0 = xp[(size_t)cbeg * 128];
    float pi1 = xp[(size_t)cbeg * 128 + NPIX];
    float pi2 = xp[(size_t)cbeg * 128 + 2 * NPIX];

    float pd[8];        // fragment-ordered d values, [si][4]
    unsigned ps[4];     // fragment-ordered packed sqrt-weights, [si][2]

    auto prep = [&](int ch) {
        float i0 = fminf(fmaxf(pi0, 0.0f), 1.0f);
        float i1 = fminf(fmaxf(pi1, 0.0f), 1.0f);
        float i2 = fminf(fmaxf(pi2, 0.0f), 1.0f);
        if (ch + 1 < cend) {
            pi0 = xp[(size_t)(ch + 1) * 128];
            pi1 = xp[(size_t)(ch + 1) * 128 + NPIX];
            pi2 = xp[(size_t)(ch + 1) * 128 + 2 * NPIX];
        }
        float l0 = lg2a(i0 + 1e-6f);
        float l1 = lg2a(i1 + 1e-6f);
        float l2 = lg2a(i2 + 1e-6f);
        float d = (g == 0) ? (l0 - l1) : (g == 1) ? (l0 - l2) : (l1 - l2);
        d *= SC;
        float s = fmaf(i0, i0, fmaf(i1, i1, fmaf(i2, i2, 1e-6f)));
        float sw = sqrta(sqrta(s));           // sqrt(Iy)
#pragma unroll
        for (int si = 0; si < 2; si++) {
            const int b0 = 16 * si + 2 * q;
            pd[4 * si + 0] = shf(d, b0);
            pd[4 * si + 1] = shf(d, b0 + 1);
            pd[4 * si + 2] = shf(d, b0 + 8);
            pd[4 * si + 3] = shf(d, b0 + 9);
            ps[2 * si + 0] = pk(shf(sw, b0),     shf(sw, b0 + 1));
            ps[2 * si + 1] = pk(shf(sw, b0 + 8), shf(sw, b0 + 9));
        }
    };

    const int nreg = cend - cbeg;
    // prologue: produce chunk cbeg into buf 0
    prep(cbeg);
#pragma unroll
    for (int k = 0; k < 8; k++) {
        const int si = k >> 2, m = k & 3;
        const float o0 = oo[2 * m], o1 = oo[2 * m + 1];
        uint4 v;
        v.x = kv(pd[4 * si + 0] - o0, pd[4 * si + 1] - o0, ps[2 * si]);
        v.y = kv(pd[4 * si + 0] - o1, pd[4 * si + 1] - o1, ps[2 * si]);
        v.z = kv(pd[4 * si + 2] - o0, pd[4 * si + 3] - o0, ps[2 * si + 1]);
        v.w = kv(pd[4 * si + 2] - o1, pd[4 * si + 3] - o1, ps[2 * si + 1]);
        sts128(baseP + (uint32_t)(si * 2048 + m * 512), v);
    }
    __syncthreads();

    int32_t pDelta = BUF_BYTES, cDelta = BUF_BYTES;
#pragma unroll 1
    for (int r = 0; r < nreg - 1; r++) {
        baseP += pDelta; pDelta = -pDelta;    // produce -> other buffer
        prep(cbeg + r + 1);
#pragma unroll
        for (int k = 0; k < 8; k++) {
            // consume K-step k from current buffer (immediate offsets)
            uint4 A0 = lds128(baseA + (uint32_t)(k * 2048));
            uint4 A1 = lds128(baseA + (uint32_t)(k * 2048 + 512));
            uint4 W0 = lds128(baseB + (uint32_t)(k * 2048));
            uint4 W1 = lds128(baseB + (uint32_t)(k * 2048 + 512));
            mma16816(acc[0][0], (const unsigned*)&A0, W0.x, W0.z);
            mma16816(acc[1][0], (const unsigned*)&A1, W0.x, W0.z);
            mma16816(acc[0][1], (const unsigned*)&A0, W0.y, W0.w);
            mma16816(acc[1][1], (const unsigned*)&A1, W0.y, W0.w);
            mma16816(acc[0][2], (const unsigned*)&A0, W1.x, W1.z);
            mma16816(acc[1][2], (const unsigned*)&A1, W1.x, W1.z);
            mma16816(acc[0][3], (const unsigned*)&A0, W1.y, W1.w);
            mma16816(acc[1][3], (const unsigned*)&A1, W1.y, W1.w);
            // produce block k of next chunk into the other buffer
            const int si = k >> 2, m = k & 3;
            const float o0 = oo[2 * m], o1 = oo[2 * m + 1];
            uint4 v;
            v.x = kv(pd[4 * si + 0] - o0, pd[4 * si + 1] - o0, ps[2 * si]);
            v.y = kv(pd[4 * si + 0] - o1, pd[4 * si + 1] - o1, ps[2 * si]);
            v.z = kv(pd[4 * si + 2] - o0, pd[4 * si + 3] - o0, ps[2 * si + 1]);
            v.w = kv(pd[4 * si + 2] - o1, pd[4 * si + 3] - o1, ps[2 * si + 1]);
            sts128(baseP + (uint32_t)(si * 2048 + m * 512), v);
        }
        __syncthreads();
        baseA += cDelta; baseB += cDelta; cDelta = -cDelta;
    }
    // final region: consume only
#pragma unroll
    for (int k = 0; k < 8; k++) {
        uint4 A0 = lds128(baseA + (uint32_t)(k * 2048));
        uint4 A1 = lds128(baseA + (uint32_t)(k * 2048 + 512));
        uint4 W0 = lds128(baseB + (uint32_t)(k * 2048));
        uint4 W1 = lds128(baseB + (uint32_t)(k * 2048 + 512));
        mma16816(acc[0][0], (const unsigned*)&A0, W0.x, W0.z);
        mma16816(acc[1][0], (const unsigned*)&A1, W0.x, W0.z);
        mma16816(acc[0][1], (const unsigned*)&A0, W0.y, W0.w);
        mma16816(acc[1][1], (const unsigned*)&A1, W0.y, W0.w);
        mma16816(acc[0][2], (const unsigned*)&A0, W1.x, W1.z);
        mma16816(acc[1][2], (const unsigned*)&A1, W1.x, W1.z);
        mma16816(acc[0][3], (const unsigned*)&A0, W1.y, W1.w);
        mma16816(acc[1][3], (const unsigned*)&A1, W1.y, W1.w);
    }

    // store this warp's 32x32 quadrant (non-atomic, private slot)
    float* dst = g_part + ((size_t)bx * 3 + g) * (H * H);
    const int r = L >> 2;
    const int qq = (L & 3) * 2;
#pragma unroll
    for (int m = 0; m < 2; m++)
#pragma unroll
        for (int jl = 0; jl < 4; jl++) {
            const int row0 = (2 * mi + m) * 16 + r;
            const int col = (4 * ni + jl) * 8 + qq;
            *(float2*)(dst + row0 * H + col)       = make_float2(acc[m][jl][0], acc[m][jl][1]);
            *(float2*)(dst + (row0 + 8) * H + col) = make_float2(acc[m][jl][2], acc[m][jl][3]);
        }

    // fused totals: per-warp sum of accs -> smem -> g_psum[bx]
    float wsum = 0.0f;
#pragma unroll
    for (int m = 0; m < 2; m++)
#pragma unroll
        for (int jl = 0; jl < 4; jl++)
            wsum += (acc[m][jl][0] + acc[m][jl][1]) + (acc[m][jl][2] + acc[m][jl][3]);
#pragma unroll
    for (int off = 16; off > 0; off >>= 1)
        wsum += __shfl_xor_sync(0xffffffffu, wsum, off);
    __syncthreads();                       // consumes of img are done; reuse as scratch
    float* sscr = (float*)img;
    if (L == 0) sscr[w] = wsum;
    __syncthreads();
    if (tid == 0) {
        float t = 0.0f;
#pragma unroll
        for (int k = 0; k < 12; k++) t += sscr[k];
        g_psum[bx] = t;
    }
}

// grid (16, 24), 256 threads. Sums NSPLIT splits with the channel reversal
// mapping AND normalizes by the per-sample total (from g_psum) in one pass.
// All NSPLIT loads issued in one fully-unrolled batch (MLP = 37) so the
// strided L2/DRAM latency is paid once, not in 5 serialized waves.
__global__ void hist_reduce(float* __restrict__ out) {
    const int lc = blockIdx.y;
    const int c = lc % 3, lidx = lc / 3;
    const int e = blockIdx.x * 256 + threadIdx.x;  // 0..4095
    const int u = e >> 6, v = e & 63;
    int se;
    if (c == 0)      se = e;                        // identity
    else if (c == 1) se = ((63 - u) << 6) | v;      // row reversal
    else             se = 4095 - e;                 // row+col reversal

    const float* __restrict__ src =
        g_part + ((size_t)(lidx * NSPLIT) * 3 + c) * (H * H) + se;

    // batch ALL loads first (front-batched LDGs, full MLP)
    float vals[NSPLIT];
#pragma unroll
    for (int sp = 0; sp < NSPLIT; sp++)
        vals[sp] = src[(size_t)sp * 3 * (H * H)];

    // per-sample total from per-CTA partials (overlaps with vals latency)
    __shared__ float tshare[NSPLIT];
    if (threadIdx.x < NSPLIT)
        tshare[threadIdx.x] = g_psum[lidx * NSPLIT + threadIdx.x];
    __syncthreads();
    float tot = 1e-6f;
#pragma unroll
    for (int k = 0; k < NSPLIT; k++) tot += tshare[k];   // broadcast LDS
    const float inv = 1.0f / tot;

    // tree-sum (pairwise for ILP)
    float s = 0.0f;
    {
        float p0 = 0.0f, p1 = 0.0f, p2 = 0.0f, p3 = 0.0f;
#pragma unroll
        for (int sp = 0; sp + 4 <= NSPLIT; sp += 4) {
            p0 += vals[sp + 0];
            p1 += vals[sp + 1];
            p2 += vals[sp + 2];
            p3 += vals[sp + 3];
        }
#pragma unroll
        for (int sp = (NSPLIT / 4) * 4; sp < NSPLIT; sp++) p0 += vals[sp];
        s = (p0 + p1) + (p2 + p3);
    }
    out[lc * (H * H) + e] = s * inv;
}

extern "C" void kernel_launch(void* const* d_in, const int* in_sizes, int n_in,
                              void* d_out, int out_size) {
    const float* x = (const float*)d_in[0];
    float* out = (float*)d_out;
    (void)in_sizes; (void)n_in; (void)out_size;

    cudaFuncSetAttribute(hist_main, cudaFuncAttributeMaxDynamicSharedMemorySize,
                         SMEM_BYTES);
    hist_main<<<NCTA, 384, SMEM_BYTES>>>(x);
    hist_reduce<<<dim3(16, 24), 256>>>(out);
}